// round 4
// baseline (speedup 1.0000x reference)
#include <cuda_runtime.h>
#include <cstdint>

// LoopyBeliefPropagation: B=8, S=128, MAX_ITER=3
//
// Algebra (d = m1 - m0, m normalized over q):
//   d2[j,k] = db2[k] - db1[k]  (the softplus(s_sib) term cancels between iters)
//   => per (i,b) slab the only O(S^2) work is C[k] = sum_{k'} v_{k'} *
//      softplus(s_sib[b,k,i,k']), then a scalar epilogue:
//      d2[k] = v_k (T + C[k] - ln2*Nv);  S0 = sum v_k softplus(d2);  S1 = sum v_k d2
//      out0[j] = v_i v_j (pe0[j]-S0);  out1[j] = v_i v_j (pe1[j]+S1-S0)
//
// R4: persistent CTAs (296) + dynamic slab tickets; lane l covers
// k' = l + 32c so invalid k' chunks (c >= cmax, warp-uniform) skip whole
// LDG+MUFU warp-instructions; folded 8-row shuffle reduction (9 shfl vs 40).

#define S_DIM 128
#define NSLAB (8 * S_DIM)
#define GRID_CTAS 296
#define LN2F 0.69314718055994530942f

__device__ unsigned int g_ticket;

__global__ void init_ticket_kernel() { g_ticket = GRID_CTAS; }

__device__ __forceinline__ float softplus_f(float x) {
    float e = __expf(-fabsf(x));
    return fmaxf(x, 0.0f) + __logf(1.0f + e);
}

__global__ __launch_bounds__(512, 2)
void lbp_kernel(const float* __restrict__ s_edge,
                const float* __restrict__ s_sib,
                const unsigned char* __restrict__ mask_raw,
                float* __restrict__ out)
{
    __shared__ float sm_v[S_DIM];
    __shared__ float sm_pe0[S_DIM];
    __shared__ float sm_pe1[S_DIM];
    __shared__ float sm_C[S_DIM];
    __shared__ float sm_pT[4], sm_pN[4], sm_p0[4], sm_p1[4];
    __shared__ unsigned int sm_next;

    const int tid  = threadIdx.x;
    const int w    = tid >> 5;
    const int lane = tid & 31;
    const unsigned int* mask_w = reinterpret_cast<const unsigned int*>(mask_raw);

    // ---- One-time mask element-width detection (batch-0 diagonal must be
    // v[0]=0, v[1]=1, monotone non-increasing). R2 evidence: 4-byte elements.
    int predA = 1;
    if (tid < S_DIM) {
        unsigned char vj  = mask_raw[tid * (S_DIM + 1)] != 0;
        unsigned char vj1 = (tid < S_DIM - 1)
                          ? (mask_raw[(tid + 1) * (S_DIM + 1)] != 0) : 0;
        if (tid == 0)              predA = (vj == 0);
        else if (tid == 1)         predA = (vj == 1) && (vj >= vj1);
        else if (tid < S_DIM - 1)  predA = (vj >= vj1);
    }
    const int okA = __syncthreads_and(predA);

    unsigned int slab = blockIdx.x;
    while (slab < NSLAB) {
        const int i  = slab & (S_DIM - 1);
        const int bb = slab >> 7;

        // Prefetch next ticket (latency hidden behind this slab's work).
        if (tid == 0) sm_next = atomicAdd(&g_ticket, 1u);

        // ---- Phase 0: per-j scalars + warp partials for T, Nv ----
        if (tid < S_DIM) {
            const int j = tid;
            const size_t e = (size_t)(bb * S_DIM + j) * S_DIM + j;  // diagonal
            bool vb = okA ? (mask_raw[e] != 0) : (mask_w[e] != 0);
            float vf = vb ? 1.0f : 0.0f;
            sm_v[j] = vf;
            const float2 pe = *reinterpret_cast<const float2*>(
                s_edge + ((size_t)(bb * S_DIM + j) * S_DIM + i) * 2);
            sm_pe0[j] = pe.x;
            sm_pe1[j] = pe.y;
            float t = vf * (pe.y - pe.x);
            float n = vf;
            #pragma unroll
            for (int off = 16; off; off >>= 1) {
                t += __shfl_xor_sync(0xffffffffu, t, off);
                n += __shfl_xor_sync(0xffffffffu, n, off);
            }
            if (lane == 0) { sm_pT[w] = t; sm_pN[w] = n; }
        }
        __syncthreads();  // B1

        const unsigned int nxt = sm_next;  // safe: written before B1

        // ---- Early out: invalid i -> slab output is all zeros ----
        if (sm_v[i] == 0.0f) {
            if (tid < S_DIM) {
                *reinterpret_cast<float2*>(
                    out + ((size_t)(bb * S_DIM + tid) * S_DIM + i) * 2) =
                    make_float2(0.0f, 0.0f);
            }
            slab = nxt;
            __syncthreads();  // protect smem before next iteration's writes
            continue;
        }

        const float Nv = sm_pN[0] + sm_pN[1] + sm_pN[2] + sm_pN[3];
        // valid j are exactly 1..Nv  =>  highest valid index is (int)Nv
        const int cmax = (((int)Nv) >> 5) + 1;   // in {2,3,4}

        // ---- Phase 1: C[j] = sum_{k'} v_{k'} softplus(s_sib[b,j,i,k']) ----
        // Warp w owns rows j = w + 16*r (r=0..7); lane covers k' = lane + 32c.
        {
            float vkc[4];
            #pragma unroll
            for (int c = 0; c < 4; c++)
                vkc[c] = (c < cmax) ? sm_v[c * 32 + lane] : 0.0f;

            const float* sbase = s_sib
                + (size_t)bb * (S_DIM * S_DIM * S_DIM) + (size_t)i * S_DIM;

            float p[8];
            #pragma unroll
            for (int r = 0; r < 8; r++) {
                const int j = w + 16 * r;               // warp-uniform
                float a = 0.0f;
                if (sm_v[j] != 0.0f) {                  // warp-uniform branch
                    const float* srow = sbase + (size_t)j * (S_DIM * S_DIM);
                    float x[4];
                    #pragma unroll
                    for (int c = 0; c < 4; c++)
                        if (c < cmax) x[c] = srow[c * 32 + lane];
                    #pragma unroll
                    for (int c = 0; c < 4; c++)
                        if (c < cmax) a = fmaf(vkc[c], softplus_f(x[c]), a);
                }
                p[r] = a;
            }

            // Folded reduction: 8 row-sums in 9 shuffles.
            const bool b4 = (lane & 16) != 0;
            const bool b3 = (lane & 8)  != 0;
            const bool b2 = (lane & 4)  != 0;
            float q[4];
            #pragma unroll
            for (int r = 0; r < 4; r++) {
                float mine  = b4 ? p[r + 4] : p[r];
                float other = b4 ? p[r]     : p[r + 4];
                q[r] = mine + __shfl_xor_sync(0xffffffffu, other, 16);
            }
            float u[2];
            #pragma unroll
            for (int r = 0; r < 2; r++) {
                float mine  = b3 ? q[r + 2] : q[r];
                float other = b3 ? q[r]     : q[r + 2];
                u[r] = mine + __shfl_xor_sync(0xffffffffu, other, 8);
            }
            float mine  = b2 ? u[1] : u[0];
            float other = b2 ? u[0] : u[1];
            float s = mine + __shfl_xor_sync(0xffffffffu, other, 4);
            s += __shfl_xor_sync(0xffffffffu, s, 2);
            s += __shfl_xor_sync(0xffffffffu, s, 1);
            // lane holds row rho = bit2 + 2*bit3 + 4*bit4 (j = w + 16*rho)
            if ((lane & 3) == 0) {
                const int rho = (b2 ? 1 : 0) + (b3 ? 2 : 0) + (b4 ? 4 : 0);
                sm_C[w + 16 * rho] = s;
            }
        }
        __syncthreads();  // B2

        // ---- Phase 2: d2[k] = v_k (T + C[k] - ln2*Nv); reduce S0, S1 ----
        if (tid < S_DIM) {
            const float T  = sm_pT[0] + sm_pT[1] + sm_pT[2] + sm_pT[3];
            const float vj = sm_v[tid];
            const float d2 = vj * (T + sm_C[tid] - LN2F * Nv);
            float s0 = vj * softplus_f(d2);
            float s1 = vj * d2;
            #pragma unroll
            for (int off = 16; off; off >>= 1) {
                s0 += __shfl_xor_sync(0xffffffffu, s0, off);
                s1 += __shfl_xor_sync(0xffffffffu, s1, off);
            }
            if (lane == 0) { sm_p0[w] = s0; sm_p1[w] = s1; }
        }
        __syncthreads();  // B3

        // ---- Phase 3: write marginals[b, j, i, :] ----
        if (tid < S_DIM) {
            const float S0 = sm_p0[0] + sm_p0[1] + sm_p0[2] + sm_p0[3];
            const float S1 = sm_p1[0] + sm_p1[1] + sm_p1[2] + sm_p1[3];
            const float vj = sm_v[tid];
            float o0 = vj * (sm_pe0[tid] - S0);
            float o1 = vj * (sm_pe1[tid] + (S1 - S0));
            *reinterpret_cast<float2*>(
                out + ((size_t)(bb * S_DIM + tid) * S_DIM + i) * 2) =
                make_float2(o0, o1);
        }
        slab = nxt;
        __syncthreads();  // protect smem before next iteration's writes
    }
}

extern "C" void kernel_launch(void* const* d_in, const int* in_sizes, int n_in,
                              void* d_out, int out_size) {
    // Remap by element counts: s_edge 262144, s_sib 16777216, mask 131072.
    const float* s_edge = nullptr;
    const float* s_sib  = nullptr;
    const unsigned char* mask = nullptr;
    for (int t = 0; t < n_in; t++) {
        if (in_sizes[t] == 262144)        s_edge = (const float*)d_in[t];
        else if (in_sizes[t] == 16777216) s_sib  = (const float*)d_in[t];
        else if (in_sizes[t] == 131072)   mask   = (const unsigned char*)d_in[t];
    }
    float* out = (float*)d_out;
    (void)out_size;

    init_ticket_kernel<<<1, 1>>>();
    lbp_kernel<<<GRID_CTAS, 512>>>(s_edge, s_sib, mask, out);
}

// round 5
// speedup vs baseline: 1.4766x; 1.4766x over previous
#include <cuda_runtime.h>
#include <cstdint>

// LoopyBeliefPropagation: B=8, S=128, MAX_ITER=3
//
// Algebra (d = m1 - m0, m normalized over q):
//   d2[j,k] = db2[k] - db1[k]  (the softplus(s_sib) term cancels between iters)
//   => per (i,b) slab the only O(S^2) work is C[k] = sum_{k'} v_{k'} *
//      softplus(s_sib[b,k,i,k']), then a scalar epilogue:
//      d2[k] = v_k (T + C[k] - ln2*Nv);  S0 = sum v_k softplus(d2);  S1 = sum v_k d2
//      out0[j] = v_i v_j (pe0[j]-S0);  out1[j] = v_i v_j (pe1[j]+S1-S0)
//
// R5: 128-thread CTAs, one slab each, grid 1024 -> 8 CTAs/SM = 8 slabs in
// flight per SM and a SINGLE wave (1024 <= 148*8). Loads stay front-batched
// float4 (8 rows prefetched per group, MLP=8 — R4's regression was losing
// this). Invalid rows skipped warp-uniformly; invalid k' lane-tail loads
// predicated off (rv zero-initialized so softplus(0)*vk=0 contributions).

#define S_DIM 128
#define LN2F 0.69314718055994530942f

__device__ __forceinline__ float softplus_f(float x) {
    float e = __expf(-fabsf(x));
    return fmaxf(x, 0.0f) + __logf(1.0f + e);
}

__global__ __launch_bounds__(128, 8)
void lbp_kernel(const float* __restrict__ s_edge,
                const float* __restrict__ s_sib,
                const unsigned char* __restrict__ mask_raw,
                float* __restrict__ out)
{
    __shared__ float sm_v[S_DIM];
    __shared__ float sm_pe0[S_DIM];
    __shared__ float sm_pe1[S_DIM];
    __shared__ float sm_C[S_DIM];
    __shared__ float sm_pT[4], sm_pN[4], sm_p0[4], sm_p1[4];

    const int slab = blockIdx.x;
    const int i   = slab & (S_DIM - 1);
    const int bb  = slab >> 7;
    const int tid  = threadIdx.x;       // 0..127, one j per thread
    const int w    = tid >> 5;
    const int lane = tid & 31;
    const unsigned int* mask_w = reinterpret_cast<const unsigned int*>(mask_raw);

    // ---- Mask element-width detection on batch-0 diagonal (v[0]=0, v[1]=1,
    // monotone non-increasing). R2 evidence: 4-byte elements; keep it robust.
    int predA = 1;
    {
        unsigned char vj  = mask_raw[tid * (S_DIM + 1)] != 0;
        unsigned char vj1 = (tid < S_DIM - 1)
                          ? (mask_raw[(tid + 1) * (S_DIM + 1)] != 0) : 0;
        if (tid == 0)              predA = (vj == 0);
        else if (tid == 1)         predA = (vj == 1) && (vj >= vj1);
        else if (tid < S_DIM - 1)  predA = (vj >= vj1);
    }
    const int okA = __syncthreads_and(predA);

    // ---- Phase 0: per-j scalars + warp partials for T, Nv ----
    {
        const int j = tid;
        const size_t e = (size_t)(bb * S_DIM + j) * S_DIM + j;  // diagonal
        bool vb = okA ? (mask_raw[e] != 0) : (mask_w[e] != 0);
        float vf = vb ? 1.0f : 0.0f;
        sm_v[j] = vf;
        const float2 pe = *reinterpret_cast<const float2*>(
            s_edge + ((size_t)(bb * S_DIM + j) * S_DIM + i) * 2);
        sm_pe0[j] = pe.x;
        sm_pe1[j] = pe.y;
        float t = vf * (pe.y - pe.x);
        float n = vf;
        #pragma unroll
        for (int off = 16; off; off >>= 1) {
            t += __shfl_xor_sync(0xffffffffu, t, off);
            n += __shfl_xor_sync(0xffffffffu, n, off);
        }
        if (lane == 0) { sm_pT[w] = t; sm_pN[w] = n; }
    }
    __syncthreads();  // B1

    // ---- Early out: invalid i -> slab output is all zeros ----
    if (sm_v[i] == 0.0f) {
        *reinterpret_cast<float2*>(
            out + ((size_t)(bb * S_DIM + tid) * S_DIM + i) * 2) =
            make_float2(0.0f, 0.0f);
        return;
    }

    const float Nv = sm_pN[0] + sm_pN[1] + sm_pN[2] + sm_pN[3];
    const int   lv = (int)Nv;               // valid j are exactly 1..lv

    // ---- Phase 1: C[j] = sum_{k'} v_{k'} softplus(s_sib[b,j,i,k']) ----
    // Warp w owns rows j in [32w, 32w+32), in 4 groups of 8 prefetched rows.
    // Lane covers k' = 4*lane .. 4*lane+3 (one float4 = whole row per warp).
    {
        const float4 vk4 = reinterpret_cast<const float4*>(sm_v)[lane];
        const bool lane_ok = (4 * lane <= lv);   // any of the 4 k' valid
        const float* sbase = s_sib
            + (size_t)bb * (S_DIM * S_DIM * S_DIM) + (size_t)i * S_DIM;

        const bool b4 = (lane & 16) != 0;
        const bool b3 = (lane & 8)  != 0;
        const bool b2 = (lane & 4)  != 0;

        #pragma unroll
        for (int g = 0; g < 4; g++) {
            const int jbase = w * 32 + g * 8;

            float4 rv[8];
            #pragma unroll
            for (int r = 0; r < 8; r++) {
                rv[r] = make_float4(0.0f, 0.0f, 0.0f, 0.0f);
                if (sm_v[jbase + r] != 0.0f && lane_ok)
                    rv[r] = reinterpret_cast<const float4*>(
                        sbase + (size_t)(jbase + r) * (S_DIM * S_DIM))[lane];
            }

            float p[8];
            #pragma unroll
            for (int r = 0; r < 8; r++) {
                float a = 0.0f;
                if (sm_v[jbase + r] != 0.0f) {       // warp-uniform branch
                    a =      vk4.x * softplus_f(rv[r].x);
                    a = fmaf(vk4.y, softplus_f(rv[r].y), a);
                    a = fmaf(vk4.z, softplus_f(rv[r].z), a);
                    a = fmaf(vk4.w, softplus_f(rv[r].w), a);
                }
                p[r] = a;
            }

            // Folded reduction: 8 row-sums in 9 shuffles.
            float q[4];
            #pragma unroll
            for (int r = 0; r < 4; r++) {
                float mine  = b4 ? p[r + 4] : p[r];
                float other = b4 ? p[r]     : p[r + 4];
                q[r] = mine + __shfl_xor_sync(0xffffffffu, other, 16);
            }
            float u[2];
            #pragma unroll
            for (int r = 0; r < 2; r++) {
                float mine  = b3 ? q[r + 2] : q[r];
                float other = b3 ? q[r]     : q[r + 2];
                u[r] = mine + __shfl_xor_sync(0xffffffffu, other, 8);
            }
            float mine  = b2 ? u[1] : u[0];
            float other = b2 ? u[0] : u[1];
            float s = mine + __shfl_xor_sync(0xffffffffu, other, 4);
            s += __shfl_xor_sync(0xffffffffu, s, 2);
            s += __shfl_xor_sync(0xffffffffu, s, 1);
            if ((lane & 3) == 0) {
                const int rho = (b2 ? 1 : 0) + (b3 ? 2 : 0) + (b4 ? 4 : 0);
                sm_C[jbase + rho] = s;
            }
        }
    }
    __syncthreads();  // B2

    // ---- Phase 2: d2[k] = v_k (T + C[k] - ln2*Nv); reduce S0, S1 ----
    {
        const float T  = sm_pT[0] + sm_pT[1] + sm_pT[2] + sm_pT[3];
        const float vj = sm_v[tid];
        const float d2 = vj * (T + sm_C[tid] - LN2F * Nv);
        float s0 = vj * softplus_f(d2);
        float s1 = vj * d2;
        #pragma unroll
        for (int off = 16; off; off >>= 1) {
            s0 += __shfl_xor_sync(0xffffffffu, s0, off);
            s1 += __shfl_xor_sync(0xffffffffu, s1, off);
        }
        if (lane == 0) { sm_p0[w] = s0; sm_p1[w] = s1; }
    }
    __syncthreads();  // B3

    // ---- Phase 3: write marginals[b, j, i, :] ----
    {
        const float S0 = sm_p0[0] + sm_p0[1] + sm_p0[2] + sm_p0[3];
        const float S1 = sm_p1[0] + sm_p1[1] + sm_p1[2] + sm_p1[3];
        const float vj = sm_v[tid];
        float o0 = vj * (sm_pe0[tid] - S0);
        float o1 = vj * (sm_pe1[tid] + (S1 - S0));
        *reinterpret_cast<float2*>(
            out + ((size_t)(bb * S_DIM + tid) * S_DIM + i) * 2) =
            make_float2(o0, o1);
    }
}

extern "C" void kernel_launch(void* const* d_in, const int* in_sizes, int n_in,
                              void* d_out, int out_size) {
    // Remap by element counts: s_edge 262144, s_sib 16777216, mask 131072.
    const float* s_edge = nullptr;
    const float* s_sib  = nullptr;
    const unsigned char* mask = nullptr;
    for (int t = 0; t < n_in; t++) {
        if (in_sizes[t] == 262144)        s_edge = (const float*)d_in[t];
        else if (in_sizes[t] == 16777216) s_sib  = (const float*)d_in[t];
        else if (in_sizes[t] == 131072)   mask   = (const unsigned char*)d_in[t];
    }
    float* out = (float*)d_out;
    (void)out_size;

    lbp_kernel<<<8 * S_DIM, 128>>>(s_edge, s_sib, mask, out);
}

// round 6
// speedup vs baseline: 1.4906x; 1.0094x over previous
#include <cuda_runtime.h>
#include <cstdint>

// LoopyBeliefPropagation: B=8, S=128, MAX_ITER=3
//
// Algebra (d = m1 - m0, m normalized over q): d2[j,k] = db2[k] - db1[k]
// (softplus(s_sib) cancels between iterations), so per (i,b) slab the only
// O(S^2) work is C[k] = sum_{k'} v_{k'} softplus(s_sib[b,k,i,k']) plus a
// scalar epilogue. One 128-thread CTA per slab, grid 1024, single wave.
//
// R6: softplus via EX2 + degree-6 polynomial (no LG2), polynomial evaluated
// pairwise with packed fma.rn.f32x2. Per-row warp cost drops from 8 MUFU
// (64 SMSP-cyc, chained) to 4 MUFU + ~22 packed-FMA (44 cyc, unchained).
//   softplus(x) = max(x,0) + g(z),  z = 2*exp(-|x|) - 1 = EX2(1 - |x|*log2e)-1
//   g(z) = Horner(b6..b0), coefficients from the Chebyshev expansion of
//   ln(3+z) on [-1,1] (rho = 2*sqrt(2)-3), abs err <= ~6e-6.

#define S_DIM 128
#define LN2F 0.69314718055994530942f
#define NL2E 1.4426950408889634f   // log2(e)

// ---- packed f32x2 helpers ----
__device__ __forceinline__ uint64_t pk2(float lo, float hi) {
    uint64_t r;
    asm("mov.b64 %0, {%1, %2};" : "=l"(r) : "f"(lo), "f"(hi));
    return r;
}
__device__ __forceinline__ uint64_t fma2(uint64_t a, uint64_t b, uint64_t c) {
    uint64_t d;
    asm("fma.rn.f32x2 %0, %1, %2, %3;" : "=l"(d) : "l"(a), "l"(b), "l"(c));
    return d;
}
__device__ __forceinline__ uint64_t add2(uint64_t a, uint64_t b) {
    uint64_t d;
    asm("add.rn.f32x2 %0, %1, %2;" : "=l"(d) : "l"(a), "l"(b));
    return d;
}
__device__ __forceinline__ float red2(uint64_t a) {
    float lo, hi;
    asm("mov.b64 {%0, %1}, %2;" : "=f"(lo), "=f"(hi) : "l"(a));
    return lo + hi;
}
__device__ __forceinline__ float ex2f(float x) {
    float y;
    asm("ex2.approx.f32 %0, %1;" : "=f"(y) : "f"(x));
    return y;
}

// Polynomial coefficients for g(z) ~= log1p(e), z = 2e-1 in [-1,1]
#define PB0  0.40545900f
#define PB1  0.33334200f
#define PB2 -0.05556080f
#define PB3  0.01227890f
#define PB4 -0.00305808f
#define PB5  0.00095157f
#define PB6 -0.00027211f

// acc += vk2 * softplus2(x0, x1)   (packed)
__device__ __forceinline__ uint64_t sp2_acc(float x0, float x1,
                                            uint64_t vk2, uint64_t acc) {
    float e0 = ex2f(fmaf(fabsf(x0), -NL2E, 1.0f));   // 2*exp(-|x0|)
    float e1 = ex2f(fmaf(fabsf(x1), -NL2E, 1.0f));
    uint64_t z = add2(pk2(e0, e1), pk2(-1.0f, -1.0f));
    uint64_t g = pk2(PB6, PB6);
    g = fma2(g, z, pk2(PB5, PB5));
    g = fma2(g, z, pk2(PB4, PB4));
    g = fma2(g, z, pk2(PB3, PB3));
    g = fma2(g, z, pk2(PB2, PB2));
    g = fma2(g, z, pk2(PB1, PB1));
    g = fma2(g, z, pk2(PB0, PB0));
    uint64_t sp = add2(pk2(fmaxf(x0, 0.0f), fmaxf(x1, 0.0f)), g);
    return fma2(vk2, sp, acc);
}

__device__ __forceinline__ float softplus_poly(float x) {
    float z = ex2f(fmaf(fabsf(x), -NL2E, 1.0f)) - 1.0f;
    float g = PB6;
    g = fmaf(g, z, PB5);
    g = fmaf(g, z, PB4);
    g = fmaf(g, z, PB3);
    g = fmaf(g, z, PB2);
    g = fmaf(g, z, PB1);
    g = fmaf(g, z, PB0);
    return fmaxf(x, 0.0f) + g;
}

__global__ __launch_bounds__(128, 7)
void lbp_kernel(const float* __restrict__ s_edge,
                const float* __restrict__ s_sib,
                const unsigned char* __restrict__ mask_raw,
                float* __restrict__ out)
{
    __shared__ float sm_v[S_DIM];
    __shared__ float sm_pe0[S_DIM];
    __shared__ float sm_pe1[S_DIM];
    __shared__ float sm_C[S_DIM];
    __shared__ float sm_pT[4], sm_pN[4], sm_p0[4], sm_p1[4];

    const int slab = blockIdx.x;
    const int i   = slab & (S_DIM - 1);
    const int bb  = slab >> 7;
    const int tid  = threadIdx.x;       // 0..127, one j per thread
    const int w    = tid >> 5;
    const int lane = tid & 31;
    const unsigned int* mask_w = reinterpret_cast<const unsigned int*>(mask_raw);

    // ---- Mask element-width detection on batch-0 diagonal (v[0]=0, v[1]=1,
    // monotone non-increasing). R2 evidence: 4-byte elements; keep it robust.
    int predA = 1;
    {
        unsigned char vj  = mask_raw[tid * (S_DIM + 1)] != 0;
        unsigned char vj1 = (tid < S_DIM - 1)
                          ? (mask_raw[(tid + 1) * (S_DIM + 1)] != 0) : 0;
        if (tid == 0)              predA = (vj == 0);
        else if (tid == 1)         predA = (vj == 1) && (vj >= vj1);
        else if (tid < S_DIM - 1)  predA = (vj >= vj1);
    }
    const int okA = __syncthreads_and(predA);

    // ---- Phase 0: per-j scalars + warp partials for T, Nv ----
    {
        const int j = tid;
        const size_t e = (size_t)(bb * S_DIM + j) * S_DIM + j;  // diagonal
        bool vb = okA ? (mask_raw[e] != 0) : (mask_w[e] != 0);
        float vf = vb ? 1.0f : 0.0f;
        sm_v[j] = vf;
        const float2 pe = *reinterpret_cast<const float2*>(
            s_edge + ((size_t)(bb * S_DIM + j) * S_DIM + i) * 2);
        sm_pe0[j] = pe.x;
        sm_pe1[j] = pe.y;
        float t = vf * (pe.y - pe.x);
        float n = vf;
        #pragma unroll
        for (int off = 16; off; off >>= 1) {
            t += __shfl_xor_sync(0xffffffffu, t, off);
            n += __shfl_xor_sync(0xffffffffu, n, off);
        }
        if (lane == 0) { sm_pT[w] = t; sm_pN[w] = n; }
    }
    __syncthreads();  // B1

    // ---- Early out: invalid i -> slab output is all zeros ----
    if (sm_v[i] == 0.0f) {
        *reinterpret_cast<float2*>(
            out + ((size_t)(bb * S_DIM + tid) * S_DIM + i) * 2) =
            make_float2(0.0f, 0.0f);
        return;
    }

    const float Nv = sm_pN[0] + sm_pN[1] + sm_pN[2] + sm_pN[3];
    const int   lv = (int)Nv;               // valid j are exactly 1..lv

    // ---- Phase 1: C[j] = sum_{k'} v_{k'} softplus(s_sib[b,j,i,k']) ----
    // Warp w owns rows j in [32w, 32w+32): 8 groups of 4 prefetched rows.
    // Lane covers k' = 4*lane .. 4*lane+3 (one float4 = whole row per warp).
    {
        const float4 vk4 = reinterpret_cast<const float4*>(sm_v)[lane];
        const uint64_t vk01 = pk2(vk4.x, vk4.y);
        const uint64_t vk23 = pk2(vk4.z, vk4.w);
        const bool lane_ok = (4 * lane <= lv);   // any of the 4 k' valid
        const float* sbase = s_sib
            + (size_t)bb * (S_DIM * S_DIM * S_DIM) + (size_t)i * S_DIM;

        const bool b4 = (lane & 16) != 0;
        const bool b3 = (lane & 8)  != 0;

        #pragma unroll
        for (int g = 0; g < 8; g++) {
            const int jbase = w * 32 + g * 4;

            float4 rv[4];
            #pragma unroll
            for (int r = 0; r < 4; r++) {
                rv[r] = make_float4(0.0f, 0.0f, 0.0f, 0.0f);
                if (sm_v[jbase + r] != 0.0f && lane_ok)
                    rv[r] = reinterpret_cast<const float4*>(
                        sbase + (size_t)(jbase + r) * (S_DIM * S_DIM))[lane];
            }

            float p[4];
            #pragma unroll
            for (int r = 0; r < 4; r++) {
                float a = 0.0f;
                if (sm_v[jbase + r] != 0.0f) {       // warp-uniform branch
                    uint64_t acc = pk2(0.0f, 0.0f);
                    acc = sp2_acc(rv[r].x, rv[r].y, vk01, acc);
                    acc = sp2_acc(rv[r].z, rv[r].w, vk23, acc);
                    a = red2(acc);
                }
                p[r] = a;
            }

            // Folded reduction: 4 row-sums in 6 shuffles.
            float q[2];
            #pragma unroll
            for (int r = 0; r < 2; r++) {
                float mine  = b4 ? p[r + 2] : p[r];
                float other = b4 ? p[r]     : p[r + 2];
                q[r] = mine + __shfl_xor_sync(0xffffffffu, other, 16);
            }
            float mine  = b3 ? q[1] : q[0];
            float other = b3 ? q[0] : q[1];
            float s = mine + __shfl_xor_sync(0xffffffffu, other, 8);
            s += __shfl_xor_sync(0xffffffffu, s, 4);
            s += __shfl_xor_sync(0xffffffffu, s, 2);
            s += __shfl_xor_sync(0xffffffffu, s, 1);
            if ((lane & 7) == 0) {
                const int rho = (b3 ? 1 : 0) + (b4 ? 2 : 0);
                sm_C[jbase + rho] = s;
            }
        }
    }
    __syncthreads();  // B2

    // ---- Phase 2: d2[k] = v_k (T + C[k] - ln2*Nv); reduce S0, S1 ----
    {
        const float T  = sm_pT[0] + sm_pT[1] + sm_pT[2] + sm_pT[3];
        const float vj = sm_v[tid];
        const float d2 = vj * (T + sm_C[tid] - LN2F * Nv);
        float s0 = vj * softplus_poly(d2);
        float s1 = vj * d2;
        #pragma unroll
        for (int off = 16; off; off >>= 1) {
            s0 += __shfl_xor_sync(0xffffffffu, s0, off);
            s1 += __shfl_xor_sync(0xffffffffu, s1, off);
        }
        if (lane == 0) { sm_p0[w] = s0; sm_p1[w] = s1; }
    }
    __syncthreads();  // B3

    // ---- Phase 3: write marginals[b, j, i, :] ----
    {
        const float S0 = sm_p0[0] + sm_p0[1] + sm_p0[2] + sm_p0[3];
        const float S1 = sm_p1[0] + sm_p1[1] + sm_p1[2] + sm_p1[3];
        const float vj = sm_v[tid];
        float o0 = vj * (sm_pe0[tid] - S0);
        float o1 = vj * (sm_pe1[tid] + (S1 - S0));
        *reinterpret_cast<float2*>(
            out + ((size_t)(bb * S_DIM + tid) * S_DIM + i) * 2) =
            make_float2(o0, o1);
    }
}

extern "C" void kernel_launch(void* const* d_in, const int* in_sizes, int n_in,
                              void* d_out, int out_size) {
    // Remap by element counts: s_edge 262144, s_sib 16777216, mask 131072.
    const float* s_edge = nullptr;
    const float* s_sib  = nullptr;
    const unsigned char* mask = nullptr;
    for (int t = 0; t < n_in; t++) {
        if (in_sizes[t] == 262144)        s_edge = (const float*)d_in[t];
        else if (in_sizes[t] == 16777216) s_sib  = (const float*)d_in[t];
        else if (in_sizes[t] == 131072)   mask   = (const unsigned char*)d_in[t];
    }
    float* out = (float*)d_out;
    (void)out_size;

    lbp_kernel<<<8 * S_DIM, 128>>>(s_edge, s_sib, mask, out);
}